// round 5
// baseline (speedup 1.0000x reference)
#include <cuda_runtime.h>
#include <cuda_fp16.h>
#include <math.h>
#include <stdint.h>

#define B_ 4
#define T_ 2048
#define D_ 1024
#define E_ 8
#define F_ 4096
#define N_ (B_*T_)            // 8192 tokens

// ---- GEMM tile config: CTA 128x256, warp 64x64 (2x4 warps) ----
#define BM 128
#define BN 256
#define BK 64                 // fp16 elems per k-tile (128 B rows)
#define STAGES 2
#define NTHREADS 256

// smem layout per stage (bytes): A-hi(16K), B-hi(32K), B-lo(32K)
#define OFF_AH 0
#define OFF_BH 16384
#define OFF_BL 49152
#define STAGE_BYTES 81920
#define SMEM_TOTAL (STAGES*STAGE_BYTES)    // 163840

// ---------------- device scratch ---------------------------------------------
__device__ int    g_cnt[E_];
__device__ int    g_tok[E_*N_];
__device__ float  g_gate[E_*N_];
__device__ __half g_x_h[(size_t)N_*D_];
__device__ __half g_w1t_hi[(size_t)E_*F_*D_];   // [E][F][D] K-major
__device__ __half g_w1t_lo[(size_t)E_*F_*D_];
__device__ __half g_w2t_hi[(size_t)E_*D_*F_];   // [E][D][F] K-major
__device__ __half g_w2t_lo[(size_t)E_*D_*F_];
__device__ __half g_h[(size_t)N_*2*F_];         // [N*K][F]

// ---------------- helpers -----------------------------------------------------
__device__ __forceinline__ uint32_t smem_u32(const void* p) {
    uint32_t a;
    asm("{ .reg .u64 t; cvta.to.shared.u64 t, %1; cvt.u32.u64 %0, t; }"
        : "=r"(a) : "l"(p));
    return a;
}
__device__ __forceinline__ void cp16(uint32_t dst, const void* src) {
    asm volatile("cp.async.cg.shared.global [%0], [%1], 16;"
                 :: "r"(dst), "l"(src) : "memory");
}
__device__ __forceinline__ void cp_commit() {
    asm volatile("cp.async.commit_group;" ::: "memory");
}
template<int NN>
__device__ __forceinline__ void cp_wait() {
    asm volatile("cp.async.wait_group %0;" :: "n"(NN) : "memory");
}
__device__ __forceinline__ void ldm4(uint32_t& r0, uint32_t& r1,
                                     uint32_t& r2, uint32_t& r3, uint32_t a) {
    asm volatile("ldmatrix.sync.aligned.m8n8.x4.shared.b16 {%0,%1,%2,%3}, [%4];"
                 : "=r"(r0), "=r"(r1), "=r"(r2), "=r"(r3) : "r"(a));
}
__device__ __forceinline__ void mma16816(float* c, const uint32_t* a,
                                         uint32_t b0, uint32_t b1) {
    asm volatile(
        "mma.sync.aligned.m16n8k16.row.col.f32.f16.f16.f32 "
        "{%0,%1,%2,%3}, {%4,%5,%6,%7}, {%8,%9}, {%0,%1,%2,%3};"
        : "+f"(c[0]), "+f"(c[1]), "+f"(c[2]), "+f"(c[3])
        : "r"(a[0]), "r"(a[1]), "r"(a[2]), "r"(a[3]), "r"(b0), "r"(b1));
}
__device__ __forceinline__ void split_h(float v, __half& h, __half& l) {
    h = __float2half_rn(v);
    l = __float2half_rn(v - __half2float(h));
}
__device__ __forceinline__ uint32_t pack2(__half a, __half b) {
    return (uint32_t)__half_as_ushort(a) | ((uint32_t)__half_as_ushort(b) << 16);
}
__device__ __forceinline__ float gelu_f(float v) {
    return 0.5f * v * (1.f + erff(v * 0.70710678118654752440f));
}

// ---------------- fused prep: x->fp16, w1/w2 transpose+split ------------------
#define XBLKS (N_*D_/4/NTHREADS)        // 8192
#define W1BLKS ((F_/32)*(D_/32)*E_)     // 32768
#define W2BLKS ((D_/32)*(F_/32)*E_)     // 32768

__global__ void prep_all_kernel(const float* __restrict__ x,
                                const float* __restrict__ w1,
                                const float* __restrict__ w2) {
    int bb  = blockIdx.x;
    int tid = threadIdx.x;
    if (bb < XBLKS) {
        size_t i4 = (size_t)bb * NTHREADS + tid;
        float4 v = ((const float4*)x)[i4];
        ((uint2*)g_x_h)[i4] = make_uint2(
            pack2(__float2half_rn(v.x), __float2half_rn(v.y)),
            pack2(__float2half_rn(v.z), __float2half_rn(v.w)));
        return;
    }
    __shared__ float tile[32][33];
    int tx = tid & 31, ty = tid >> 5;          // (32, 8)
    const float* w; __half* whi; __half* wlo;
    int RIN, CIN, bid;
    if (bb < XBLKS + W1BLKS) {
        bid = bb - XBLKS; w = w1; whi = g_w1t_hi; wlo = g_w1t_lo;
        RIN = D_; CIN = F_;
    } else {
        bid = bb - XBLKS - W1BLKS; w = w2; whi = g_w2t_hi; wlo = g_w2t_lo;
        RIN = F_; CIN = D_;
    }
    int cb = CIN / 32, rb = RIN / 32;
    int e   = bid / (cb * rb);
    int rem = bid % (cb * rb);
    int c0  = (rem % cb) * 32, r0 = (rem / cb) * 32;
    const float* wi = w + (size_t)e * RIN * CIN;
    #pragma unroll
    for (int i = 0; i < 4; i++)
        tile[ty + 8*i][tx] = wi[(size_t)(r0 + ty + 8*i) * CIN + c0 + tx];
    __syncthreads();
    size_t ob = (size_t)e * CIN * RIN;
    #pragma unroll
    for (int i = 0; i < 4; i++) {
        int c = c0 + ty + 8*i, r = r0 + tx;
        __half h, l;
        split_h(tile[tx][ty + 8*i], h, l);
        whi[ob + (size_t)c * RIN + r] = h;
        wlo[ob + (size_t)c * RIN + r] = l;
    }
}

// ---------------- gating ------------------------------------------------------
__global__ void init_kernel() { if (threadIdx.x < E_) g_cnt[threadIdx.x] = 0; }

__global__ void gate_kernel(const float* __restrict__ x,
                            const float* __restrict__ gw) {
    int gtid = blockIdx.x * blockDim.x + threadIdx.x;
    int t = gtid >> 5, lane = gtid & 31;
    if (t >= N_) return;
    const float* xr = x + (size_t)t * D_;
    float acc[E_];
    #pragma unroll
    for (int e = 0; e < E_; e++) acc[e] = 0.f;
    for (int d = lane; d < D_; d += 32) {
        float xv = xr[d];
        #pragma unroll
        for (int e = 0; e < E_; e++) acc[e] = fmaf(xv, gw[d * E_ + e], acc[e]);
    }
    #pragma unroll
    for (int e = 0; e < E_; e++)
        #pragma unroll
        for (int o = 16; o > 0; o >>= 1)
            acc[e] += __shfl_xor_sync(0xffffffffu, acc[e], o);
    if (lane == 0) {
        int i0 = 0; float v0 = acc[0];
        #pragma unroll
        for (int e = 1; e < E_; e++) if (acc[e] > v0) { v0 = acc[e]; i0 = e; }
        int i1 = -1; float v1 = -1e30f;
        #pragma unroll
        for (int e = 0; e < E_; e++) if (e != i0 && acc[e] > v1) { v1 = acc[e]; i1 = e; }
        float e1 = expf(v1 - v0), inv = 1.f / (1.f + e1);
        int p0 = atomicAdd(&g_cnt[i0], 1);
        g_tok[i0 * N_ + p0] = t;  g_gate[i0 * N_ + p0] = inv;
        int p1 = atomicAdd(&g_cnt[i1], 1);
        g_tok[i1 * N_ + p1] = t;  g_gate[i1 * N_ + p1] = e1 * inv;
    }
}

// ---------------- grouped GEMM on HMMA (2-term split: Ah*Bh + Ah*Bl) ----------
// PHASE 1: h = gelu(gather(x_h) @ w1t[e]^T + b1[e])
// PHASE 2: out += gate * (h @ w2t[e]^T + b2[e])
template<int PHASE>
__global__ __launch_bounds__(NTHREADS, 1)
void moe_gemm_kernel(const float* __restrict__ bias_g, float* __restrict__ out) {
    constexpr int KT    = (PHASE == 1) ? D_ : F_;
    constexpr int KT64  = KT / BK;
    constexpr int NFULL = (PHASE == 1) ? F_ : D_;

    int e   = blockIdx.z;
    int cnt = g_cnt[e];
    int m0  = blockIdx.y * BM;
    if (m0 >= cnt) return;
    int n0  = blockIdx.x * BN;
    int off = 0;                       // in-kernel exclusive scan (8 reads)
    #pragma unroll
    for (int j = 0; j < E_; j++) if (j < e) off += g_cnt[j];

    extern __shared__ __align__(1024) char smem[];
    uint32_t sb = smem_u32(smem);
    int tid = threadIdx.x, wid = tid >> 5, lane = tid & 31;

    const __half* Ah = (PHASE == 1) ? g_x_h : g_h;
    const __half* Bh = ((PHASE == 1) ? g_w1t_hi : g_w2t_hi) + (size_t)e * (size_t)NFULL * KT;
    const __half* Bl = ((PHASE == 1) ? g_w1t_lo : g_w2t_lo) + (size_t)e * (size_t)NFULL * KT;

    // ---- cp.async mapping: thread handles rows rbase+32i, chunk tid&7 ----
    int rbase = tid >> 3;
    int ch    = tid & 7;
    int csw   = ch ^ (rbase & 7);
    uint32_t dst_a = (uint32_t)(rbase * 128 + csw * 16);   // +4096 per row step

    const __half* a_p[4];
    #pragma unroll
    for (int i = 0; i < 4; i++) {
        int grow = min(m0 + rbase + 32 * i, cnt - 1);
        size_t arow = (PHASE == 1) ? (size_t)g_tok[e * N_ + grow]
                                   : (size_t)(off + grow);
        a_p[i] = Ah + arow * KT + ch * 8;
    }
    const __half* b_hp = Bh + (size_t)(n0 + rbase) * KT + ch * 8;
    const __half* b_lp = Bl + (size_t)(n0 + rbase) * KT + ch * 8;

    auto load_stage = [&](int kt, int slot) {
        uint32_t s0 = sb + slot * STAGE_BYTES;
        int koff = kt * BK;
        #pragma unroll
        for (int i = 0; i < 4; i++)
            cp16(s0 + OFF_AH + dst_a + i * 4096u, a_p[i] + koff);
        #pragma unroll
        for (int i = 0; i < 8; i++) {
            cp16(s0 + OFF_BH + dst_a + i * 4096u, b_hp + koff + i * (32 * KT));
            cp16(s0 + OFF_BL + dst_a + i * 4096u, b_lp + koff + i * (32 * KT));
        }
    };

    // ---- fragment address constants: warp grid 2(m) x 4(n), tile 64x64 ----
    int m_warp = (wid & 1) * 64;
    int n_warp = (wid >> 1) * 64;
    uint32_t a_rowb[4], b_rowb[4];
    #pragma unroll
    for (int mf = 0; mf < 4; mf++)
        a_rowb[mf] = (uint32_t)((m_warp + mf * 16 + (lane & 15)) * 128);
    #pragma unroll
    for (int q = 0; q < 4; q++)
        b_rowb[q] = (uint32_t)((n_warp + q * 16 + ((lane & 16) >> 1) + (lane & 7)) * 128);
    uint32_t a_chsel = (uint32_t)(lane >> 4);
    uint32_t b_chsel = (uint32_t)((lane >> 3) & 1);
    uint32_t lxor    = (uint32_t)(lane & 7);

    float acc[4][8][4];
    #pragma unroll
    for (int mf = 0; mf < 4; mf++)
        #pragma unroll
        for (int nb = 0; nb < 8; nb++)
            #pragma unroll
            for (int i = 0; i < 4; i++) acc[mf][nb][i] = 0.f;

    // ---- prologue ----
    load_stage(0, 0);
    cp_commit();

    // ---- main loop (double buffer; last iter drains fully) ----
    for (int kt = 0; kt < KT64; kt++) {
        if (kt + 1 < KT64) {
            load_stage(kt + 1, (kt + 1) & 1);
            cp_commit();
            cp_wait<1>();
        } else {
            cp_wait<0>();
        }
        __syncthreads();

        uint32_t s0 = sb + (kt & 1) * STAGE_BYTES;
        #pragma unroll
        for (int ks = 0; ks < 4; ks++) {
            uint32_t ach = (((2 * ks + a_chsel) ^ lxor) << 4);
            uint32_t bch = (((2 * ks + b_chsel) ^ lxor) << 4);
            uint32_t af[4][4];
            #pragma unroll
            for (int mf = 0; mf < 4; mf++)
                ldm4(af[mf][0], af[mf][1], af[mf][2], af[mf][3],
                     s0 + OFF_AH + a_rowb[mf] + ach);
            #pragma unroll
            for (int q = 0; q < 4; q++) {
                uint32_t bh0, bh1, bh2, bh3, bl0, bl1, bl2, bl3;
                ldm4(bh0, bh1, bh2, bh3, s0 + OFF_BH + b_rowb[q] + bch);
                ldm4(bl0, bl1, bl2, bl3, s0 + OFF_BL + b_rowb[q] + bch);
                #pragma unroll
                for (int mf = 0; mf < 4; mf++) {
                    mma16816(acc[mf][2*q],   af[mf], bh0, bh1);
                    mma16816(acc[mf][2*q],   af[mf], bl0, bl1);
                    mma16816(acc[mf][2*q+1], af[mf], bh2, bh3);
                    mma16816(acc[mf][2*q+1], af[mf], bl2, bl3);
                }
            }
        }
        __syncthreads();
    }

    // ---- epilogue ----
    const float* bias = bias_g + (size_t)e * NFULL + n0;
    #pragma unroll
    for (int mf = 0; mf < 4; mf++) {
        #pragma unroll
        for (int hh = 0; hh < 2; hh++) {
            int lr = m_warp + mf * 16 + hh * 8 + (lane >> 2);
            int r  = m0 + lr;
            if (r >= cnt) continue;
            if (PHASE == 1) {
                __half* ph = g_h + (size_t)(off + r) * F_ + n0;
                #pragma unroll
                for (int nb = 0; nb < 8; nb++) {
                    int col = n_warp + nb * 8 + 2 * (lane & 3);
                    float2 bv = *(const float2*)(bias + col);
                    float v0 = gelu_f(acc[mf][nb][hh*2]     + bv.x);
                    float v1 = gelu_f(acc[mf][nb][hh*2 + 1] + bv.y);
                    *(uint32_t*)(ph + col) =
                        pack2(__float2half_rn(v0), __float2half_rn(v1));
                }
            } else {
                int   tok = g_tok[e * N_ + r];
                float gv  = g_gate[e * N_ + r];
                float* orow = out + (size_t)tok * D_ + n0;
                #pragma unroll
                for (int nb = 0; nb < 8; nb++) {
                    int col = n_warp + nb * 8 + 2 * (lane & 3);
                    float2 bv = *(const float2*)(bias + col);
                    atomicAdd(orow + col,     gv * (acc[mf][nb][hh*2]     + bv.x));
                    atomicAdd(orow + col + 1, gv * (acc[mf][nb][hh*2 + 1] + bv.y));
                }
            }
        }
    }
}

// ---------------- launch --------------------------------------------------------
extern "C" void kernel_launch(void* const* d_in, const int* in_sizes, int n_in,
                              void* d_out, int out_size) {
    const float* x  = (const float*)d_in[0];
    const float* gw = (const float*)d_in[1];
    const float* w1 = (const float*)d_in[2];
    const float* b1 = (const float*)d_in[3];
    const float* w2 = (const float*)d_in[4];
    const float* b2 = (const float*)d_in[5];
    float* out = (float*)d_out;

    cudaFuncSetAttribute(moe_gemm_kernel<1>,
                         cudaFuncAttributeMaxDynamicSharedMemorySize, SMEM_TOTAL);
    cudaFuncSetAttribute(moe_gemm_kernel<2>,
                         cudaFuncAttributeMaxDynamicSharedMemorySize, SMEM_TOTAL);

    cudaMemsetAsync(out, 0, (size_t)out_size * sizeof(float), 0);
    prep_all_kernel<<<XBLKS + W1BLKS + W2BLKS, NTHREADS>>>(x, w1, w2);
    init_kernel<<<1, 32>>>();
    gate_kernel<<<(N_ * 32) / 256, 256>>>(x, gw);

    dim3 g1(F_/BN, N_/BM, E_);     // (16, 64, 8), cnt-guarded
    moe_gemm_kernel<1><<<g1, NTHREADS, SMEM_TOTAL>>>(b1, out);

    dim3 g2(D_/BN, N_/BM, E_);     // (4, 64, 8), cnt-guarded
    moe_gemm_kernel<2><<<g2, NTHREADS, SMEM_TOTAL>>>(b2, out);
}

// round 6
// speedup vs baseline: 1.5937x; 1.5937x over previous
#include <cuda_runtime.h>
#include <cuda_fp16.h>
#include <math.h>
#include <stdint.h>

#define B_ 4
#define T_ 2048
#define D_ 1024
#define E_ 8
#define F_ 4096
#define N_ (B_*T_)            // 8192 tokens

// ---- GEMM tile config: CTA 128x256, warp 64x64 (2x4 warps), plain fp16 ----
#define BM 128
#define BN 256
#define BK 64                 // fp16 elems per k-tile (128 B rows)
#define STAGES 4
#define NTHREADS 256

// smem layout per stage (bytes): A(16K), B(32K)
#define OFF_A 0
#define OFF_B 16384
#define STAGE_BYTES 49152
#define SMEM_TOTAL (STAGES*STAGE_BYTES)    // 196608

// ---------------- device scratch ---------------------------------------------
__device__ int    g_cnt[E_];
__device__ int    g_tok[E_*N_];
__device__ float  g_gate[E_*N_];
__device__ __half g_x_h[(size_t)N_*D_];
__device__ __half g_w1t[(size_t)E_*F_*D_];   // [E][F][D] K-major
__device__ __half g_w2t[(size_t)E_*D_*F_];   // [E][D][F] K-major
__device__ __half g_h[(size_t)N_*2*F_];      // [N*K][F]

// ---------------- helpers -----------------------------------------------------
__device__ __forceinline__ uint32_t smem_u32(const void* p) {
    uint32_t a;
    asm("{ .reg .u64 t; cvta.to.shared.u64 t, %1; cvt.u32.u64 %0, t; }"
        : "=r"(a) : "l"(p));
    return a;
}
__device__ __forceinline__ void cp16(uint32_t dst, const void* src) {
    asm volatile("cp.async.cg.shared.global [%0], [%1], 16;"
                 :: "r"(dst), "l"(src) : "memory");
}
__device__ __forceinline__ void cp_commit() {
    asm volatile("cp.async.commit_group;" ::: "memory");
}
template<int NN>
__device__ __forceinline__ void cp_wait() {
    asm volatile("cp.async.wait_group %0;" :: "n"(NN) : "memory");
}
__device__ __forceinline__ void ldm4(uint32_t& r0, uint32_t& r1,
                                     uint32_t& r2, uint32_t& r3, uint32_t a) {
    asm volatile("ldmatrix.sync.aligned.m8n8.x4.shared.b16 {%0,%1,%2,%3}, [%4];"
                 : "=r"(r0), "=r"(r1), "=r"(r2), "=r"(r3) : "r"(a));
}
__device__ __forceinline__ void mma16816(float* c, const uint32_t* a,
                                         uint32_t b0, uint32_t b1) {
    asm volatile(
        "mma.sync.aligned.m16n8k16.row.col.f32.f16.f16.f32 "
        "{%0,%1,%2,%3}, {%4,%5,%6,%7}, {%8,%9}, {%0,%1,%2,%3};"
        : "+f"(c[0]), "+f"(c[1]), "+f"(c[2]), "+f"(c[3])
        : "r"(a[0]), "r"(a[1]), "r"(a[2]), "r"(a[3]), "r"(b0), "r"(b1));
}
__device__ __forceinline__ uint32_t pack2(__half a, __half b) {
    return (uint32_t)__half_as_ushort(a) | ((uint32_t)__half_as_ushort(b) << 16);
}
__device__ __forceinline__ float gelu_f(float v) {
    return 0.5f * v * (1.f + erff(v * 0.70710678118654752440f));
}

// ---------------- fused prep: x->fp16, w1/w2 transpose->fp16 ------------------
#define XBLKS (N_*D_/4/NTHREADS)        // 8192
#define W1BLKS ((F_/32)*(D_/32)*E_)     // 32768
#define W2BLKS ((D_/32)*(F_/32)*E_)     // 32768

__global__ void prep_all_kernel(const float* __restrict__ x,
                                const float* __restrict__ w1,
                                const float* __restrict__ w2) {
    int bb  = blockIdx.x;
    int tid = threadIdx.x;
    if (bb < XBLKS) {
        size_t i4 = (size_t)bb * NTHREADS + tid;
        float4 v = ((const float4*)x)[i4];
        ((uint2*)g_x_h)[i4] = make_uint2(
            pack2(__float2half_rn(v.x), __float2half_rn(v.y)),
            pack2(__float2half_rn(v.z), __float2half_rn(v.w)));
        return;
    }
    __shared__ float tile[32][33];
    int tx = tid & 31, ty = tid >> 5;          // (32, 8)
    const float* w; __half* wt;
    int RIN, CIN, bid;
    if (bb < XBLKS + W1BLKS) {
        bid = bb - XBLKS; w = w1; wt = g_w1t; RIN = D_; CIN = F_;
    } else {
        bid = bb - XBLKS - W1BLKS; w = w2; wt = g_w2t; RIN = F_; CIN = D_;
    }
    int cb = CIN / 32, rb = RIN / 32;
    int e   = bid / (cb * rb);
    int rem = bid % (cb * rb);
    int c0  = (rem % cb) * 32, r0 = (rem / cb) * 32;
    const float* wi = w + (size_t)e * RIN * CIN;
    #pragma unroll
    for (int i = 0; i < 4; i++)
        tile[ty + 8*i][tx] = wi[(size_t)(r0 + ty + 8*i) * CIN + c0 + tx];
    __syncthreads();
    size_t ob = (size_t)e * CIN * RIN;
    #pragma unroll
    for (int i = 0; i < 4; i++) {
        int c = c0 + ty + 8*i, r = r0 + tx;
        wt[ob + (size_t)c * RIN + r] = __float2half_rn(tile[tx][ty + 8*i]);
    }
}

// ---------------- gating ------------------------------------------------------
__global__ void init_kernel() { if (threadIdx.x < E_) g_cnt[threadIdx.x] = 0; }

__global__ void gate_kernel(const float* __restrict__ x,
                            const float* __restrict__ gw) {
    int gtid = blockIdx.x * blockDim.x + threadIdx.x;
    int t = gtid >> 5, lane = gtid & 31;
    if (t >= N_) return;
    const float* xr = x + (size_t)t * D_;
    float acc[E_];
    #pragma unroll
    for (int e = 0; e < E_; e++) acc[e] = 0.f;
    for (int d = lane; d < D_; d += 32) {
        float xv = xr[d];
        #pragma unroll
        for (int e = 0; e < E_; e++) acc[e] = fmaf(xv, gw[d * E_ + e], acc[e]);
    }
    #pragma unroll
    for (int e = 0; e < E_; e++)
        #pragma unroll
        for (int o = 16; o > 0; o >>= 1)
            acc[e] += __shfl_xor_sync(0xffffffffu, acc[e], o);
    if (lane == 0) {
        int i0 = 0; float v0 = acc[0];
        #pragma unroll
        for (int e = 1; e < E_; e++) if (acc[e] > v0) { v0 = acc[e]; i0 = e; }
        int i1 = -1; float v1 = -1e30f;
        #pragma unroll
        for (int e = 0; e < E_; e++) if (e != i0 && acc[e] > v1) { v1 = acc[e]; i1 = e; }
        float e1 = expf(v1 - v0), inv = 1.f / (1.f + e1);
        int p0 = atomicAdd(&g_cnt[i0], 1);
        g_tok[i0 * N_ + p0] = t;  g_gate[i0 * N_ + p0] = inv;
        int p1 = atomicAdd(&g_cnt[i1], 1);
        g_tok[i1 * N_ + p1] = t;  g_gate[i1 * N_ + p1] = e1 * inv;
    }
}

// ---------------- grouped GEMM on HMMA (plain fp16) ---------------------------
// PHASE 1: h = gelu(gather(x_h) @ w1t[e]^T + b1[e])
// PHASE 2: out += gate * (h @ w2t[e]^T + b2[e])
template<int PHASE>
__global__ __launch_bounds__(NTHREADS, 1)
void moe_gemm_kernel(const float* __restrict__ bias_g, float* __restrict__ out) {
    constexpr int KT    = (PHASE == 1) ? D_ : F_;
    constexpr int KT64  = KT / BK;
    constexpr int NFULL = (PHASE == 1) ? F_ : D_;

    int e   = blockIdx.z;
    int cnt = g_cnt[e];
    int m0  = blockIdx.y * BM;
    if (m0 >= cnt) return;
    int n0  = blockIdx.x * BN;
    int off = 0;                       // in-kernel exclusive scan (8 reads)
    #pragma unroll
    for (int j = 0; j < E_; j++) if (j < e) off += g_cnt[j];

    extern __shared__ __align__(1024) char smem[];
    uint32_t sb = smem_u32(smem);
    int tid = threadIdx.x, wid = tid >> 5, lane = tid & 31;

    const __half* Ap = (PHASE == 1) ? g_x_h : g_h;
    const __half* Bp = ((PHASE == 1) ? g_w1t : g_w2t) + (size_t)e * (size_t)NFULL * KT;

    // ---- cp.async mapping: thread handles rows rbase+32i, chunk tid&7 ----
    int rbase = tid >> 3;
    int ch    = tid & 7;
    int csw   = ch ^ (rbase & 7);
    uint32_t dst = (uint32_t)(rbase * 128 + csw * 16);   // +4096 per 32-row step

    const __half* a_p[4];
    #pragma unroll
    for (int i = 0; i < 4; i++) {
        int grow = min(m0 + rbase + 32 * i, cnt - 1);
        size_t arow = (PHASE == 1) ? (size_t)g_tok[e * N_ + grow]
                                   : (size_t)(off + grow);
        a_p[i] = Ap + arow * KT + ch * 8;
    }
    const __half* b_p = Bp + (size_t)(n0 + rbase) * KT + ch * 8;

    auto load_stage = [&](int kt, int slot) {
        uint32_t s0 = sb + slot * STAGE_BYTES;
        int koff = kt * BK;
        #pragma unroll
        for (int i = 0; i < 4; i++)
            cp16(s0 + OFF_A + dst + i * 4096u, a_p[i] + koff);
        #pragma unroll
        for (int i = 0; i < 8; i++)
            cp16(s0 + OFF_B + dst + i * 4096u, b_p + koff + i * (32 * KT));
    };

    // ---- fragment address constants: warp grid 2(m) x 4(n), tile 64x64 ----
    int m_warp = (wid & 1) * 64;
    int n_warp = (wid >> 1) * 64;
    uint32_t a_rowb[4], b_rowb[4];
    #pragma unroll
    for (int mf = 0; mf < 4; mf++)
        a_rowb[mf] = (uint32_t)((m_warp + mf * 16 + (lane & 15)) * 128);
    #pragma unroll
    for (int q = 0; q < 4; q++)
        b_rowb[q] = (uint32_t)((n_warp + q * 16 + ((lane & 16) >> 1) + (lane & 7)) * 128);
    uint32_t a_chsel = (uint32_t)(lane >> 4);
    uint32_t b_chsel = (uint32_t)((lane >> 3) & 1);
    uint32_t lxor    = (uint32_t)(lane & 7);

    float acc[4][8][4];
    #pragma unroll
    for (int mf = 0; mf < 4; mf++)
        #pragma unroll
        for (int nb = 0; nb < 8; nb++)
            #pragma unroll
            for (int i = 0; i < 4; i++) acc[mf][nb][i] = 0.f;

    // ---- prologue: fill STAGES-1 slots ----
    #pragma unroll
    for (int p = 0; p < STAGES - 1 && p < KT64; p++) {
        load_stage(p, p);
        cp_commit();
    }

    // ---- main loop: issue load for kt+3, then drain so stage kt is ready ----
    for (int kt = 0; kt < KT64; kt++) {
        if (kt + STAGES - 1 < KT64) {
            load_stage(kt + STAGES - 1, (kt + STAGES - 1) % STAGES);
            cp_commit();
            cp_wait<STAGES - 1>();
        } else if (kt + 2 < KT64) {
            cp_wait<2>();
        } else if (kt + 1 < KT64) {
            cp_wait<1>();
        } else {
            cp_wait<0>();
        }
        __syncthreads();

        uint32_t s0 = sb + (kt % STAGES) * STAGE_BYTES;
        #pragma unroll
        for (int ks = 0; ks < 4; ks++) {
            uint32_t ach = (((2 * ks + a_chsel) ^ lxor) << 4);
            uint32_t bch = (((2 * ks + b_chsel) ^ lxor) << 4);
            uint32_t af[4][4];
            #pragma unroll
            for (int mf = 0; mf < 4; mf++)
                ldm4(af[mf][0], af[mf][1], af[mf][2], af[mf][3],
                     s0 + OFF_A + a_rowb[mf] + ach);
            #pragma unroll
            for (int q = 0; q < 4; q++) {
                uint32_t b0, b1, b2, b3;
                ldm4(b0, b1, b2, b3, s0 + OFF_B + b_rowb[q] + bch);
                #pragma unroll
                for (int mf = 0; mf < 4; mf++) {
                    mma16816(acc[mf][2*q],   af[mf], b0, b1);
                    mma16816(acc[mf][2*q+1], af[mf], b2, b3);
                }
            }
        }
        __syncthreads();
    }

    // ---- epilogue ----
    const float* bias = bias_g + (size_t)e * NFULL + n0;
    #pragma unroll
    for (int mf = 0; mf < 4; mf++) {
        #pragma unroll
        for (int hh = 0; hh < 2; hh++) {
            int lr = m_warp + mf * 16 + hh * 8 + (lane >> 2);
            int r  = m0 + lr;
            if (r >= cnt) continue;
            if (PHASE == 1) {
                __half* ph = g_h + (size_t)(off + r) * F_ + n0;
                #pragma unroll
                for (int nb = 0; nb < 8; nb++) {
                    int col = n_warp + nb * 8 + 2 * (lane & 3);
                    float2 bv = *(const float2*)(bias + col);
                    float v0 = gelu_f(acc[mf][nb][hh*2]     + bv.x);
                    float v1 = gelu_f(acc[mf][nb][hh*2 + 1] + bv.y);
                    *(uint32_t*)(ph + col) =
                        pack2(__float2half_rn(v0), __float2half_rn(v1));
                }
            } else {
                int   tok = g_tok[e * N_ + r];
                float gv  = g_gate[e * N_ + r];
                float* orow = out + (size_t)tok * D_ + n0;
                #pragma unroll
                for (int nb = 0; nb < 8; nb++) {
                    int col = n_warp + nb * 8 + 2 * (lane & 3);
                    float2 bv = *(const float2*)(bias + col);
                    atomicAdd(orow + col,     gv * (acc[mf][nb][hh*2]     + bv.x));
                    atomicAdd(orow + col + 1, gv * (acc[mf][nb][hh*2 + 1] + bv.y));
                }
            }
        }
    }
}

// ---------------- launch --------------------------------------------------------
extern "C" void kernel_launch(void* const* d_in, const int* in_sizes, int n_in,
                              void* d_out, int out_size) {
    const float* x  = (const float*)d_in[0];
    const float* gw = (const float*)d_in[1];
    const float* w1 = (const float*)d_in[2];
    const float* b1 = (const float*)d_in[3];
    const float* w2 = (const float*)d_in[4];
    const float* b2 = (const float*)d_in[5];
    float* out = (float*)d_out;

    cudaFuncSetAttribute(moe_gemm_kernel<1>,
                         cudaFuncAttributeMaxDynamicSharedMemorySize, SMEM_TOTAL);
    cudaFuncSetAttribute(moe_gemm_kernel<2>,
                         cudaFuncAttributeMaxDynamicSharedMemorySize, SMEM_TOTAL);

    cudaMemsetAsync(out, 0, (size_t)out_size * sizeof(float), 0);
    prep_all_kernel<<<XBLKS + W1BLKS + W2BLKS, NTHREADS>>>(x, w1, w2);
    init_kernel<<<1, 32>>>();
    gate_kernel<<<(N_ * 32) / 256, 256>>>(x, gw);

    dim3 g1(F_/BN, N_/BM, E_);     // (16, 64, 8), cnt-guarded
    moe_gemm_kernel<1><<<g1, NTHREADS, SMEM_TOTAL>>>(b1, out);

    dim3 g2(D_/BN, N_/BM, E_);     // (4, 64, 8), cnt-guarded
    moe_gemm_kernel<2><<<g2, NTHREADS, SMEM_TOTAL>>>(b2, out);
}

// round 7
// speedup vs baseline: 1.6812x; 1.0549x over previous
#include <cuda_runtime.h>
#include <cuda_fp16.h>
#include <math.h>
#include <stdint.h>

#define B_ 4
#define T_ 2048
#define D_ 1024
#define E_ 8
#define F_ 4096
#define N_ (B_*T_)            // 8192 tokens

// ---- GEMM tile config: CTA 128x256, warp 64x64 (2x4 warps), plain fp16 ----
#define BM 128
#define BN 256
#define BK 64                 // fp16 elems per k-tile (128 B rows)
#define STAGES 4
#define NTHREADS 256

// smem layout per stage (bytes): A(16K), B(32K)
#define OFF_A 0
#define OFF_B 16384
#define STAGE_BYTES 49152
#define SMEM_TOTAL (STAGES*STAGE_BYTES)    // 196608

// ---------------- device scratch ---------------------------------------------
__device__ int    g_cnt[E_];
__device__ int    g_tok[E_*N_];
__device__ float  g_gate[E_*N_];
__device__ __half g_x_h[(size_t)N_*D_];
__device__ __half g_w1t[(size_t)E_*F_*D_];   // [E][F][D] K-major
__device__ __half g_w2t[(size_t)E_*D_*F_];   // [E][D][F] K-major
__device__ __half g_h[(size_t)N_*2*F_];      // [N*K][F]

// ---------------- helpers -----------------------------------------------------
__device__ __forceinline__ uint32_t smem_u32(const void* p) {
    uint32_t a;
    asm("{ .reg .u64 t; cvta.to.shared.u64 t, %1; cvt.u32.u64 %0, t; }"
        : "=r"(a) : "l"(p));
    return a;
}
__device__ __forceinline__ void cp16(uint32_t dst, const void* src) {
    asm volatile("cp.async.cg.shared.global [%0], [%1], 16;"
                 :: "r"(dst), "l"(src) : "memory");
}
__device__ __forceinline__ void cp_commit() {
    asm volatile("cp.async.commit_group;" ::: "memory");
}
template<int NN>
__device__ __forceinline__ void cp_wait() {
    asm volatile("cp.async.wait_group %0;" :: "n"(NN) : "memory");
}
__device__ __forceinline__ void ldm4(uint32_t& r0, uint32_t& r1,
                                     uint32_t& r2, uint32_t& r3, uint32_t a) {
    asm volatile("ldmatrix.sync.aligned.m8n8.x4.shared.b16 {%0,%1,%2,%3}, [%4];"
                 : "=r"(r0), "=r"(r1), "=r"(r2), "=r"(r3) : "r"(a));
}
__device__ __forceinline__ void mma16816(float* c, const uint32_t* a,
                                         uint32_t b0, uint32_t b1) {
    asm volatile(
        "mma.sync.aligned.m16n8k16.row.col.f32.f16.f16.f32 "
        "{%0,%1,%2,%3}, {%4,%5,%6,%7}, {%8,%9}, {%0,%1,%2,%3};"
        : "+f"(c[0]), "+f"(c[1]), "+f"(c[2]), "+f"(c[3])
        : "r"(a[0]), "r"(a[1]), "r"(a[2]), "r"(a[3]), "r"(b0), "r"(b1));
}
__device__ __forceinline__ uint32_t pack2(__half a, __half b) {
    return (uint32_t)__half_as_ushort(a) | ((uint32_t)__half_as_ushort(b) << 16);
}
__device__ __forceinline__ float gelu_f(float v) {
    return 0.5f * v * (1.f + erff(v * 0.70710678118654752440f));
}

// ---------------- fused prep: x->fp16, w1/w2 transpose->fp16 ------------------
#define XBLKS (N_*D_/4/NTHREADS)        // 8192
#define W1BLKS ((F_/32)*(D_/32)*E_)     // 32768
#define W2BLKS ((D_/32)*(F_/32)*E_)     // 32768

__global__ void prep_all_kernel(const float* __restrict__ x,
                                const float* __restrict__ w1,
                                const float* __restrict__ w2) {
    int bb  = blockIdx.x;
    int tid = threadIdx.x;
    if (bb < XBLKS) {
        size_t i4 = (size_t)bb * NTHREADS + tid;
        float4 v = ((const float4*)x)[i4];
        ((uint2*)g_x_h)[i4] = make_uint2(
            pack2(__float2half_rn(v.x), __float2half_rn(v.y)),
            pack2(__float2half_rn(v.z), __float2half_rn(v.w)));
        return;
    }
    __shared__ float tile[32][33];
    int tx = tid & 31, ty = tid >> 5;          // (32, 8)
    const float* w; __half* wt;
    int RIN, CIN, bid;
    if (bb < XBLKS + W1BLKS) {
        bid = bb - XBLKS; w = w1; wt = g_w1t; RIN = D_; CIN = F_;
    } else {
        bid = bb - XBLKS - W1BLKS; w = w2; wt = g_w2t; RIN = F_; CIN = D_;
    }
    int cb = CIN / 32, rb = RIN / 32;
    int e   = bid / (cb * rb);
    int rem = bid % (cb * rb);
    int c0  = (rem % cb) * 32, r0 = (rem / cb) * 32;
    const float* wi = w + (size_t)e * RIN * CIN;
    #pragma unroll
    for (int i = 0; i < 4; i++)
        tile[ty + 8*i][tx] = wi[(size_t)(r0 + ty + 8*i) * CIN + c0 + tx];
    __syncthreads();
    size_t ob = (size_t)e * CIN * RIN;
    #pragma unroll
    for (int i = 0; i < 4; i++) {
        int c = c0 + ty + 8*i, r = r0 + tx;
        wt[ob + (size_t)c * RIN + r] = __float2half_rn(tile[tx][ty + 8*i]);
    }
}

// ---------------- gating ------------------------------------------------------
__global__ void init_kernel() { if (threadIdx.x < E_) g_cnt[threadIdx.x] = 0; }

__global__ void gate_kernel(const float* __restrict__ x,
                            const float* __restrict__ gw) {
    int gtid = blockIdx.x * blockDim.x + threadIdx.x;
    int t = gtid >> 5, lane = gtid & 31;
    if (t >= N_) return;
    const float* xr = x + (size_t)t * D_;
    float acc[E_];
    #pragma unroll
    for (int e = 0; e < E_; e++) acc[e] = 0.f;
    for (int d = lane; d < D_; d += 32) {
        float xv = xr[d];
        #pragma unroll
        for (int e = 0; e < E_; e++) acc[e] = fmaf(xv, gw[d * E_ + e], acc[e]);
    }
    #pragma unroll
    for (int e = 0; e < E_; e++)
        #pragma unroll
        for (int o = 16; o > 0; o >>= 1)
            acc[e] += __shfl_xor_sync(0xffffffffu, acc[e], o);
    if (lane == 0) {
        int i0 = 0; float v0 = acc[0];
        #pragma unroll
        for (int e = 1; e < E_; e++) if (acc[e] > v0) { v0 = acc[e]; i0 = e; }
        int i1 = -1; float v1 = -1e30f;
        #pragma unroll
        for (int e = 0; e < E_; e++) if (e != i0 && acc[e] > v1) { v1 = acc[e]; i1 = e; }
        float e1 = expf(v1 - v0), inv = 1.f / (1.f + e1);
        int p0 = atomicAdd(&g_cnt[i0], 1);
        g_tok[i0 * N_ + p0] = t;  g_gate[i0 * N_ + p0] = inv;
        int p1 = atomicAdd(&g_cnt[i1], 1);
        g_tok[i1 * N_ + p1] = t;  g_gate[i1 * N_ + p1] = e1 * inv;
    }
}

// ---------------- grouped GEMM on HMMA (plain fp16) ---------------------------
// PHASE 1: h = gelu(gather(x_h) @ w1t[e]^T + b1[e])
// PHASE 2: out += gate * (h @ w2t[e]^T + b2[e])
template<int PHASE>
__global__ __launch_bounds__(NTHREADS, 1)
void moe_gemm_kernel(const float* __restrict__ bias_g, float* __restrict__ out) {
    constexpr int KT    = (PHASE == 1) ? D_ : F_;
    constexpr int KT64  = KT / BK;
    constexpr int NFULL = (PHASE == 1) ? F_ : D_;

    int e   = blockIdx.z;
    int cnt = g_cnt[e];
    int m0  = blockIdx.y * BM;
    if (m0 >= cnt) return;
    int n0  = blockIdx.x * BN;
    int off = 0;                       // in-kernel exclusive scan (8 reads)
    #pragma unroll
    for (int j = 0; j < E_; j++) if (j < e) off += g_cnt[j];

    extern __shared__ __align__(1024) char smem[];
    uint32_t sb = smem_u32(smem);
    int tid = threadIdx.x, wid = tid >> 5, lane = tid & 31;

    const __half* Ap = (PHASE == 1) ? g_x_h : g_h;
    const __half* Bp = ((PHASE == 1) ? g_w1t : g_w2t) + (size_t)e * (size_t)NFULL * KT;

    // ---- cp.async mapping: thread handles rows rbase+32i, chunk tid&7 ----
    int rbase = tid >> 3;
    int ch    = tid & 7;
    int csw   = ch ^ (rbase & 7);
    uint32_t dst = (uint32_t)(rbase * 128 + csw * 16);   // +4096 per 32-row step

    const __half* a_p[4];
    #pragma unroll
    for (int i = 0; i < 4; i++) {
        int grow = min(m0 + rbase + 32 * i, cnt - 1);
        size_t arow = (PHASE == 1) ? (size_t)g_tok[e * N_ + grow]
                                   : (size_t)(off + grow);
        a_p[i] = Ap + arow * KT + ch * 8;
    }
    const __half* b_p = Bp + (size_t)(n0 + rbase) * KT + ch * 8;

    auto load_stage = [&](int kt, int slot) {
        uint32_t s0 = sb + slot * STAGE_BYTES;
        int koff = kt * BK;
        #pragma unroll
        for (int i = 0; i < 4; i++)
            cp16(s0 + OFF_A + dst + i * 4096u, a_p[i] + koff);
        #pragma unroll
        for (int i = 0; i < 8; i++)
            cp16(s0 + OFF_B + dst + i * 4096u, b_p + koff + i * (32 * KT));
    };

    // ---- fragment address constants: warp grid 2(m) x 4(n), tile 64x64 ----
    int m_warp = (wid & 1) * 64;
    int n_warp = (wid >> 1) * 64;
    uint32_t a_rowb[4], b_rowb[4];
    #pragma unroll
    for (int mf = 0; mf < 4; mf++)
        a_rowb[mf] = (uint32_t)((m_warp + mf * 16 + (lane & 15)) * 128);
    #pragma unroll
    for (int q = 0; q < 4; q++)
        b_rowb[q] = (uint32_t)((n_warp + q * 16 + ((lane & 16) >> 1) + (lane & 7)) * 128);
    uint32_t a_chsel = (uint32_t)(lane >> 4);
    uint32_t b_chsel = (uint32_t)((lane >> 3) & 1);
    uint32_t lxor    = (uint32_t)(lane & 7);

    float acc[4][8][4];
    #pragma unroll
    for (int mf = 0; mf < 4; mf++)
        #pragma unroll
        for (int nb = 0; nb < 8; nb++)
            #pragma unroll
            for (int i = 0; i < 4; i++) acc[mf][nb][i] = 0.f;

    // fragment double buffers (software pipeline over ks)
    uint32_t afr[2][4][4], bfr[2][4][4];

    auto ld_frags = [&](uint32_t s0, int ks, int buf) {
        uint32_t ach = (((2 * (uint32_t)ks + a_chsel) ^ lxor) << 4);
        uint32_t bch = (((2 * (uint32_t)ks + b_chsel) ^ lxor) << 4);
        #pragma unroll
        for (int mf = 0; mf < 4; mf++)
            ldm4(afr[buf][mf][0], afr[buf][mf][1], afr[buf][mf][2], afr[buf][mf][3],
                 s0 + OFF_A + a_rowb[mf] + ach);
        #pragma unroll
        for (int q = 0; q < 4; q++)
            ldm4(bfr[buf][q][0], bfr[buf][q][1], bfr[buf][q][2], bfr[buf][q][3],
                 s0 + OFF_B + b_rowb[q] + bch);
    };

    // ---- prologue: fill STAGES-1 slots ----
    #pragma unroll
    for (int p = 0; p < STAGES - 1; p++) {
        if (p < KT64) load_stage(p, p);
        cp_commit();
    }

    // ---- main loop: ONE barrier per k-tile ----
    // Safety: the barrier at iter kt follows compute(kt-1) in program order,
    // so the load issued at iter kt into slot (kt+3)%4 == (kt-1)%4 cannot
    // overwrite a buffer any warp is still reading.
    for (int kt = 0; kt < KT64; kt++) {
        cp_wait<STAGES - 2>();     // slot kt complete (2 newest groups may pend)
        __syncthreads();

        uint32_t s0 = sb + (kt % STAGES) * STAGE_BYTES;
        ld_frags(s0, 0, 0);
        #pragma unroll
        for (int ks = 0; ks < 4; ks++) {
            int cur = ks & 1;
            if (ks < 3) ld_frags(s0, ks + 1, cur ^ 1);
            #pragma unroll
            for (int q = 0; q < 4; q++) {
                #pragma unroll
                for (int mf = 0; mf < 4; mf++) {
                    mma16816(acc[mf][2*q],   afr[cur][mf], bfr[cur][q][0], bfr[cur][q][1]);
                    mma16816(acc[mf][2*q+1], afr[cur][mf], bfr[cur][q][2], bfr[cur][q][3]);
                }
            }
        }

        if (kt + STAGES - 1 < KT64)
            load_stage(kt + STAGES - 1, (kt + STAGES - 1) % STAGES);
        cp_commit();               // commit every iter (empty groups ok)
    }

    // ---- epilogue ----
    const float* bias = bias_g + (size_t)e * NFULL + n0;
    #pragma unroll
    for (int mf = 0; mf < 4; mf++) {
        #pragma unroll
        for (int hh = 0; hh < 2; hh++) {
            int lr = m_warp + mf * 16 + hh * 8 + (lane >> 2);
            int r  = m0 + lr;
            if (r >= cnt) continue;
            if (PHASE == 1) {
                __half* ph = g_h + (size_t)(off + r) * F_ + n0;
                #pragma unroll
                for (int nb = 0; nb < 8; nb++) {
                    int col = n_warp + nb * 8 + 2 * (lane & 3);
                    float2 bv = *(const float2*)(bias + col);
                    float v0 = gelu_f(acc[mf][nb][hh*2]     + bv.x);
                    float v1 = gelu_f(acc[mf][nb][hh*2 + 1] + bv.y);
                    *(uint32_t*)(ph + col) =
                        pack2(__float2half_rn(v0), __float2half_rn(v1));
                }
            } else {
                int   tok = g_tok[e * N_ + r];
                float gv  = g_gate[e * N_ + r];
                float* orow = out + (size_t)tok * D_ + n0;
                #pragma unroll
                for (int nb = 0; nb < 8; nb++) {
                    int col = n_warp + nb * 8 + 2 * (lane & 3);
                    float2 bv = *(const float2*)(bias + col);
                    atomicAdd(orow + col,     gv * (acc[mf][nb][hh*2]     + bv.x));
                    atomicAdd(orow + col + 1, gv * (acc[mf][nb][hh*2 + 1] + bv.y));
                }
            }
        }
    }
}

// ---------------- launch --------------------------------------------------------
extern "C" void kernel_launch(void* const* d_in, const int* in_sizes, int n_in,
                              void* d_out, int out_size) {
    const float* x  = (const float*)d_in[0];
    const float* gw = (const float*)d_in[1];
    const float* w1 = (const float*)d_in[2];
    const float* b1 = (const float*)d_in[3];
    const float* w2 = (const float*)d_in[4];
    const float* b2 = (const float*)d_in[5];
    float* out = (float*)d_out;

    cudaFuncSetAttribute(moe_gemm_kernel<1>,
                         cudaFuncAttributeMaxDynamicSharedMemorySize, SMEM_TOTAL);
    cudaFuncSetAttribute(moe_gemm_kernel<2>,
                         cudaFuncAttributeMaxDynamicSharedMemorySize, SMEM_TOTAL);

    cudaMemsetAsync(out, 0, (size_t)out_size * sizeof(float), 0);
    prep_all_kernel<<<XBLKS + W1BLKS + W2BLKS, NTHREADS>>>(x, w1, w2);
    init_kernel<<<1, 32>>>();
    gate_kernel<<<(N_ * 32) / 256, 256>>>(x, gw);

    dim3 g1(F_/BN, N_/BM, E_);     // (16, 64, 8), cnt-guarded
    moe_gemm_kernel<1><<<g1, NTHREADS, SMEM_TOTAL>>>(b1, out);

    dim3 g2(D_/BN, N_/BM, E_);     // (4, 64, 8), cnt-guarded
    moe_gemm_kernel<2><<<g2, NTHREADS, SMEM_TOTAL>>>(b2, out);
}

// round 8
// speedup vs baseline: 1.7073x; 1.0155x over previous
#include <cuda_runtime.h>
#include <cuda_fp16.h>
#include <math.h>
#include <stdint.h>

#define B_ 4
#define T_ 2048
#define D_ 1024
#define E_ 8
#define F_ 4096
#define N_ (B_*T_)            // 8192 tokens

// ---- GEMM tile config: CTA 128x256, 16 warps (4m x 4n), warp tile 32x64 ----
#define BM 128
#define BN 256
#define BK 64                 // fp16 elems per k-tile (128 B rows)
#define STAGES 4
#define NTHREADS 512

// smem layout per stage (bytes): A(16K), B(32K)
#define OFF_A 0
#define OFF_B 16384
#define STAGE_BYTES 49152
#define SMEM_TOTAL (STAGES*STAGE_BYTES)    // 196608

// ---------------- device scratch ---------------------------------------------
__device__ int    g_cnt[E_];
__device__ int    g_tok[E_*N_];
__device__ float  g_gate[E_*N_];
__device__ __half g_x_h[(size_t)N_*D_];
__device__ __half g_w1t[(size_t)E_*F_*D_];   // [E][F][D] K-major
__device__ __half g_w2t[(size_t)E_*D_*F_];   // [E][D][F] K-major
__device__ __half g_h[(size_t)N_*2*F_];      // [N*K][F]

// ---------------- helpers -----------------------------------------------------
__device__ __forceinline__ uint32_t smem_u32(const void* p) {
    uint32_t a;
    asm("{ .reg .u64 t; cvta.to.shared.u64 t, %1; cvt.u32.u64 %0, t; }"
        : "=r"(a) : "l"(p));
    return a;
}
__device__ __forceinline__ void cp16(uint32_t dst, const void* src) {
    asm volatile("cp.async.cg.shared.global [%0], [%1], 16;"
                 :: "r"(dst), "l"(src) : "memory");
}
__device__ __forceinline__ void cp_commit() {
    asm volatile("cp.async.commit_group;" ::: "memory");
}
template<int NN>
__device__ __forceinline__ void cp_wait() {
    asm volatile("cp.async.wait_group %0;" :: "n"(NN) : "memory");
}
__device__ __forceinline__ void ldm4(uint32_t& r0, uint32_t& r1,
                                     uint32_t& r2, uint32_t& r3, uint32_t a) {
    asm volatile("ldmatrix.sync.aligned.m8n8.x4.shared.b16 {%0,%1,%2,%3}, [%4];"
                 : "=r"(r0), "=r"(r1), "=r"(r2), "=r"(r3) : "r"(a));
}
__device__ __forceinline__ void mma16816(float* c, const uint32_t* a,
                                         uint32_t b0, uint32_t b1) {
    asm volatile(
        "mma.sync.aligned.m16n8k16.row.col.f32.f16.f16.f32 "
        "{%0,%1,%2,%3}, {%4,%5,%6,%7}, {%8,%9}, {%0,%1,%2,%3};"
        : "+f"(c[0]), "+f"(c[1]), "+f"(c[2]), "+f"(c[3])
        : "r"(a[0]), "r"(a[1]), "r"(a[2]), "r"(a[3]), "r"(b0), "r"(b1));
}
__device__ __forceinline__ uint32_t pack2(__half a, __half b) {
    return (uint32_t)__half_as_ushort(a) | ((uint32_t)__half_as_ushort(b) << 16);
}
__device__ __forceinline__ float gelu_f(float v) {
    return 0.5f * v * (1.f + erff(v * 0.70710678118654752440f));
}

// ---------------- fused prep: x->fp16, w1/w2 transpose->fp16 ------------------
#define PT 256
#define XBLKS (N_*D_/4/PT)              // 8192
#define W1BLKS ((F_/32)*(D_/32)*E_)     // 32768
#define W2BLKS ((D_/32)*(F_/32)*E_)     // 32768

__global__ void prep_all_kernel(const float* __restrict__ x,
                                const float* __restrict__ w1,
                                const float* __restrict__ w2) {
    int bb  = blockIdx.x;
    int tid = threadIdx.x;
    if (bb < XBLKS) {
        size_t i4 = (size_t)bb * PT + tid;
        float4 v = ((const float4*)x)[i4];
        ((uint2*)g_x_h)[i4] = make_uint2(
            pack2(__float2half_rn(v.x), __float2half_rn(v.y)),
            pack2(__float2half_rn(v.z), __float2half_rn(v.w)));
        return;
    }
    __shared__ float tile[32][33];
    int tx = tid & 31, ty = tid >> 5;          // (32, 8)
    const float* w; __half* wt;
    int RIN, CIN, bid;
    if (bb < XBLKS + W1BLKS) {
        bid = bb - XBLKS; w = w1; wt = g_w1t; RIN = D_; CIN = F_;
    } else {
        bid = bb - XBLKS - W1BLKS; w = w2; wt = g_w2t; RIN = F_; CIN = D_;
    }
    int cb = CIN / 32, rb = RIN / 32;
    int e   = bid / (cb * rb);
    int rem = bid % (cb * rb);
    int c0  = (rem % cb) * 32, r0 = (rem / cb) * 32;
    const float* wi = w + (size_t)e * RIN * CIN;
    #pragma unroll
    for (int i = 0; i < 4; i++)
        tile[ty + 8*i][tx] = wi[(size_t)(r0 + ty + 8*i) * CIN + c0 + tx];
    __syncthreads();
    size_t ob = (size_t)e * CIN * RIN;
    #pragma unroll
    for (int i = 0; i < 4; i++) {
        int c = c0 + ty + 8*i, r = r0 + tx;
        wt[ob + (size_t)c * RIN + r] = __float2half_rn(tile[tx][ty + 8*i]);
    }
}

// ---------------- gating ------------------------------------------------------
__global__ void init_kernel() { if (threadIdx.x < E_) g_cnt[threadIdx.x] = 0; }

__global__ void gate_kernel(const float* __restrict__ x,
                            const float* __restrict__ gw) {
    int gtid = blockIdx.x * blockDim.x + threadIdx.x;
    int t = gtid >> 5, lane = gtid & 31;
    if (t >= N_) return;
    const float* xr = x + (size_t)t * D_;
    float acc[E_];
    #pragma unroll
    for (int e = 0; e < E_; e++) acc[e] = 0.f;
    for (int d = lane; d < D_; d += 32) {
        float xv = xr[d];
        #pragma unroll
        for (int e = 0; e < E_; e++) acc[e] = fmaf(xv, gw[d * E_ + e], acc[e]);
    }
    #pragma unroll
    for (int e = 0; e < E_; e++)
        #pragma unroll
        for (int o = 16; o > 0; o >>= 1)
            acc[e] += __shfl_xor_sync(0xffffffffu, acc[e], o);
    if (lane == 0) {
        int i0 = 0; float v0 = acc[0];
        #pragma unroll
        for (int e = 1; e < E_; e++) if (acc[e] > v0) { v0 = acc[e]; i0 = e; }
        int i1 = -1; float v1 = -1e30f;
        #pragma unroll
        for (int e = 0; e < E_; e++) if (e != i0 && acc[e] > v1) { v1 = acc[e]; i1 = e; }
        float e1 = expf(v1 - v0), inv = 1.f / (1.f + e1);
        int p0 = atomicAdd(&g_cnt[i0], 1);
        g_tok[i0 * N_ + p0] = t;  g_gate[i0 * N_ + p0] = inv;
        int p1 = atomicAdd(&g_cnt[i1], 1);
        g_tok[i1 * N_ + p1] = t;  g_gate[i1 * N_ + p1] = e1 * inv;
    }
}

// ---------------- grouped GEMM on HMMA (plain fp16, 16 warps) -----------------
// PHASE 1: h = gelu(gather(x_h) @ w1t[e]^T + b1[e])
// PHASE 2: out += gate * (h @ w2t[e]^T + b2[e])
template<int PHASE>
__global__ __launch_bounds__(NTHREADS, 1)
void moe_gemm_kernel(const float* __restrict__ bias_g, float* __restrict__ out) {
    constexpr int KT    = (PHASE == 1) ? D_ : F_;
    constexpr int KT64  = KT / BK;
    constexpr int NFULL = (PHASE == 1) ? F_ : D_;

    int e   = blockIdx.z;
    int cnt = g_cnt[e];
    int m0  = blockIdx.y * BM;
    if (m0 >= cnt) return;
    int n0  = blockIdx.x * BN;
    int off = 0;                       // in-kernel exclusive scan (8 reads)
    #pragma unroll
    for (int j = 0; j < E_; j++) if (j < e) off += g_cnt[j];

    extern __shared__ __align__(1024) char smem[];
    uint32_t sb = smem_u32(smem);
    int tid = threadIdx.x, wid = tid >> 5, lane = tid & 31;

    const __half* Ap = (PHASE == 1) ? g_x_h : g_h;
    const __half* Bp = ((PHASE == 1) ? g_w1t : g_w2t) + (size_t)e * (size_t)NFULL * KT;

    // ---- cp.async mapping: 512 threads; A rows 128 (2/thr), B rows 256 (4/thr)
    int rbase = tid >> 3;              // 0..63
    int ch    = tid & 7;
    int csw   = ch ^ (rbase & 7);
    uint32_t dst = (uint32_t)(rbase * 128 + csw * 16);   // +8192 per 64-row step

    const __half* a_p[2];
    #pragma unroll
    for (int i = 0; i < 2; i++) {
        int grow = min(m0 + rbase + 64 * i, cnt - 1);
        size_t arow = (PHASE == 1) ? (size_t)g_tok[e * N_ + grow]
                                   : (size_t)(off + grow);
        a_p[i] = Ap + arow * KT + ch * 8;
    }
    const __half* b_p = Bp + (size_t)(n0 + rbase) * KT + ch * 8;

    auto load_stage = [&](int kt, int slot) {
        uint32_t s0 = sb + slot * STAGE_BYTES;
        int koff = kt * BK;
        #pragma unroll
        for (int i = 0; i < 2; i++)
            cp16(s0 + OFF_A + dst + i * 8192u, a_p[i] + koff);
        #pragma unroll
        for (int i = 0; i < 4; i++)
            cp16(s0 + OFF_B + dst + i * 8192u, b_p + koff + i * (64 * KT));
    };

    // ---- fragment address constants: warp grid 4(m) x 4(n), tile 32x64 ----
    int m_warp = (wid & 3) * 32;
    int n_warp = (wid >> 2) * 64;
    uint32_t a_rowb[2], b_rowb[4];
    #pragma unroll
    for (int mf = 0; mf < 2; mf++)
        a_rowb[mf] = (uint32_t)((m_warp + mf * 16 + (lane & 15)) * 128);
    #pragma unroll
    for (int q = 0; q < 4; q++)
        b_rowb[q] = (uint32_t)((n_warp + q * 16 + ((lane & 16) >> 1) + (lane & 7)) * 128);
    uint32_t a_chsel = (uint32_t)(lane >> 4);
    uint32_t b_chsel = (uint32_t)((lane >> 3) & 1);
    uint32_t lxor    = (uint32_t)(lane & 7);

    float acc[2][8][4];
    #pragma unroll
    for (int mf = 0; mf < 2; mf++)
        #pragma unroll
        for (int nb = 0; nb < 8; nb++)
            #pragma unroll
            for (int i = 0; i < 4; i++) acc[mf][nb][i] = 0.f;

    // ---- prologue: fill STAGES-1 slots ----
    #pragma unroll
    for (int p = 0; p < STAGES - 1; p++) {
        if (p < KT64) load_stage(p, p);
        cp_commit();
    }

    // ---- main loop: one barrier per k-tile (see R7 safety argument) ----
    for (int kt = 0; kt < KT64; kt++) {
        cp_wait<STAGES - 2>();
        __syncthreads();

        uint32_t s0 = sb + (kt % STAGES) * STAGE_BYTES;
        #pragma unroll
        for (int ks = 0; ks < 4; ks++) {
            uint32_t ach = (((2 * (uint32_t)ks + a_chsel) ^ lxor) << 4);
            uint32_t bch = (((2 * (uint32_t)ks + b_chsel) ^ lxor) << 4);
            uint32_t af[2][4], bf[4][4];
            #pragma unroll
            for (int mf = 0; mf < 2; mf++)
                ldm4(af[mf][0], af[mf][1], af[mf][2], af[mf][3],
                     s0 + OFF_A + a_rowb[mf] + ach);
            #pragma unroll
            for (int q = 0; q < 4; q++)
                ldm4(bf[q][0], bf[q][1], bf[q][2], bf[q][3],
                     s0 + OFF_B + b_rowb[q] + bch);
            #pragma unroll
            for (int q = 0; q < 4; q++) {
                #pragma unroll
                for (int mf = 0; mf < 2; mf++) {
                    mma16816(acc[mf][2*q],   af[mf], bf[q][0], bf[q][1]);
                    mma16816(acc[mf][2*q+1], af[mf], bf[q][2], bf[q][3]);
                }
            }
        }

        if (kt + STAGES - 1 < KT64)
            load_stage(kt + STAGES - 1, (kt + STAGES - 1) % STAGES);
        cp_commit();
    }

    // ---- epilogue ----
    const float* bias = bias_g + (size_t)e * NFULL + n0;
    #pragma unroll
    for (int mf = 0; mf < 2; mf++) {
        #pragma unroll
        for (int hh = 0; hh < 2; hh++) {
            int lr = m_warp + mf * 16 + hh * 8 + (lane >> 2);
            int r  = m0 + lr;
            if (r >= cnt) continue;
            if (PHASE == 1) {
                __half* ph = g_h + (size_t)(off + r) * F_ + n0;
                #pragma unroll
                for (int nb = 0; nb < 8; nb++) {
                    int col = n_warp + nb * 8 + 2 * (lane & 3);
                    float2 bv = *(const float2*)(bias + col);
                    float v0 = gelu_f(acc[mf][nb][hh*2]     + bv.x);
                    float v1 = gelu_f(acc[mf][nb][hh*2 + 1] + bv.y);
                    *(uint32_t*)(ph + col) =
                        pack2(__float2half_rn(v0), __float2half_rn(v1));
                }
            } else {
                int   tok = g_tok[e * N_ + r];
                float gv  = g_gate[e * N_ + r];
                float* orow = out + (size_t)tok * D_ + n0;
                #pragma unroll
                for (int nb = 0; nb < 8; nb++) {
                    int col = n_warp + nb * 8 + 2 * (lane & 3);
                    float2 bv = *(const float2*)(bias + col);
                    atomicAdd(orow + col,     gv * (acc[mf][nb][hh*2]     + bv.x));
                    atomicAdd(orow + col + 1, gv * (acc[mf][nb][hh*2 + 1] + bv.y));
                }
            }
        }
    }
}

// ---------------- launch --------------------------------------------------------
extern "C" void kernel_launch(void* const* d_in, const int* in_sizes, int n_in,
                              void* d_out, int out_size) {
    const float* x  = (const float*)d_in[0];
    const float* gw = (const float*)d_in[1];
    const float* w1 = (const float*)d_in[2];
    const float* b1 = (const float*)d_in[3];
    const float* w2 = (const float*)d_in[4];
    const float* b2 = (const float*)d_in[5];
    float* out = (float*)d_out;

    cudaFuncSetAttribute(moe_gemm_kernel<1>,
                         cudaFuncAttributeMaxDynamicSharedMemorySize, SMEM_TOTAL);
    cudaFuncSetAttribute(moe_gemm_kernel<2>,
                         cudaFuncAttributeMaxDynamicSharedMemorySize, SMEM_TOTAL);

    cudaMemsetAsync(out, 0, (size_t)out_size * sizeof(float), 0);
    prep_all_kernel<<<XBLKS + W1BLKS + W2BLKS, PT>>>(x, w1, w2);
    init_kernel<<<1, 32>>>();
    gate_kernel<<<(N_ * 32) / 256, 256>>>(x, gw);

    dim3 g1(F_/BN, N_/BM, E_);     // (16, 64, 8), cnt-guarded
    moe_gemm_kernel<1><<<g1, NTHREADS, SMEM_TOTAL>>>(b1, out);

    dim3 g2(D_/BN, N_/BM, E_);     // (4, 64, 8), cnt-guarded
    moe_gemm_kernel<2><<<g2, NTHREADS, SMEM_TOTAL>>>(b2, out);
}

// round 9
// speedup vs baseline: 1.7603x; 1.0311x over previous
#include <cuda_runtime.h>
#include <cuda_fp16.h>
#include <math.h>
#include <stdint.h>

#define B_ 4
#define T_ 2048
#define D_ 1024
#define E_ 8
#define F_ 4096
#define N_ (B_*T_)            // 8192 tokens

// ---- GEMM tile config: CTA 128x256, 16 warps (4m x 4n), warp 32x64 ----
#define BM 128
#define BN 256
#define BK 128                // fp16 elems per k-tile (256 B rows)
#define STAGES 2
#define NTHREADS 512

// smem per stage (bytes): A(32K), B(64K)
#define OFF_A 0
#define OFF_B 32768
#define STAGE_BYTES 98304
#define SMEM_TOTAL (STAGES*STAGE_BYTES)    // 196608

// ---------------- device scratch ---------------------------------------------
__device__ int    g_cnt[E_];
__device__ int    g_tok[E_*N_];
__device__ float  g_gate[E_*N_];
__device__ __half g_x_h[(size_t)N_*D_];
__device__ __half g_w1t[(size_t)E_*F_*D_];   // [E][F][D] K-major
__device__ __half g_w2t[(size_t)E_*D_*F_];   // [E][D][F] K-major
__device__ __half g_h[(size_t)N_*2*F_];      // [N*K][F]

// ---------------- helpers -----------------------------------------------------
__device__ __forceinline__ uint32_t smem_u32(const void* p) {
    uint32_t a;
    asm("{ .reg .u64 t; cvta.to.shared.u64 t, %1; cvt.u32.u64 %0, t; }"
        : "=r"(a) : "l"(p));
    return a;
}
__device__ __forceinline__ void cp16(uint32_t dst, const void* src) {
    asm volatile("cp.async.cg.shared.global [%0], [%1], 16;"
                 :: "r"(dst), "l"(src) : "memory");
}
__device__ __forceinline__ void cp_commit() {
    asm volatile("cp.async.commit_group;" ::: "memory");
}
template<int NN>
__device__ __forceinline__ void cp_wait() {
    asm volatile("cp.async.wait_group %0;" :: "n"(NN) : "memory");
}
__device__ __forceinline__ void ldm4(uint32_t& r0, uint32_t& r1,
                                     uint32_t& r2, uint32_t& r3, uint32_t a) {
    asm volatile("ldmatrix.sync.aligned.m8n8.x4.shared.b16 {%0,%1,%2,%3}, [%4];"
                 : "=r"(r0), "=r"(r1), "=r"(r2), "=r"(r3) : "r"(a));
}
__device__ __forceinline__ void mma16816(float* c, const uint32_t* a,
                                         uint32_t b0, uint32_t b1) {
    asm volatile(
        "mma.sync.aligned.m16n8k16.row.col.f32.f16.f16.f32 "
        "{%0,%1,%2,%3}, {%4,%5,%6,%7}, {%8,%9}, {%0,%1,%2,%3};"
        : "+f"(c[0]), "+f"(c[1]), "+f"(c[2]), "+f"(c[3])
        : "r"(a[0]), "r"(a[1]), "r"(a[2]), "r"(a[3]), "r"(b0), "r"(b1));
}
__device__ __forceinline__ uint32_t pack2(__half a, __half b) {
    return (uint32_t)__half_as_ushort(a) | ((uint32_t)__half_as_ushort(b) << 16);
}
__device__ __forceinline__ float gelu_f(float v) {
    return 0.5f * v * (1.f + erff(v * 0.70710678118654752440f));
}

// ---------------- fused prep: x->fp16, w1/w2 transpose->fp16 ------------------
// weight transpose blocks: 32 cols x 64 rows, packed uint32 stores
#define PT 256
#define XBLKS (N_*D_/4/PT)                  // 8192
#define W1BLKS ((F_/32)*(D_/64)*E_)         // 16384
#define W2BLKS ((D_/32)*(F_/64)*E_)         // 16384

__global__ void prep_all_kernel(const float* __restrict__ x,
                                const float* __restrict__ w1,
                                const float* __restrict__ w2) {
    int bb  = blockIdx.x;
    int tid = threadIdx.x;
    if (bb < XBLKS) {
        size_t i4 = (size_t)bb * PT + tid;
        float4 v = ((const float4*)x)[i4];
        ((uint2*)g_x_h)[i4] = make_uint2(
            pack2(__float2half_rn(v.x), __float2half_rn(v.y)),
            pack2(__float2half_rn(v.z), __float2half_rn(v.w)));
        return;
    }
    __shared__ float tile[64][33];
    int tx = tid & 31, ty = tid >> 5;          // (32, 8)
    const float* w; __half* wt;
    int RIN, CIN, bid;
    if (bb < XBLKS + W1BLKS) {
        bid = bb - XBLKS; w = w1; wt = g_w1t; RIN = D_; CIN = F_;
    } else {
        bid = bb - XBLKS - W1BLKS; w = w2; wt = g_w2t; RIN = F_; CIN = D_;
    }
    int cb = CIN / 32, rb = RIN / 64;
    int e   = bid / (cb * rb);
    int rem = bid % (cb * rb);
    int c0  = (rem % cb) * 32, r0 = (rem / cb) * 64;
    const float* wi = w + (size_t)e * RIN * CIN;
    #pragma unroll
    for (int i = 0; i < 8; i++)
        tile[ty + 8*i][tx] = wi[(size_t)(r0 + ty + 8*i) * CIN + c0 + tx];
    __syncthreads();
    size_t ob = (size_t)e * CIN * RIN;
    #pragma unroll
    for (int j = 0; j < 4; j++) {
        int c = ty * 4 + j;
        uint32_t v = pack2(__float2half_rn(tile[2*tx][c]),
                           __float2half_rn(tile[2*tx + 1][c]));
        *(uint32_t*)(wt + ob + (size_t)(c0 + c) * RIN + r0 + 2*tx) = v;
    }
}

// ---------------- gating ------------------------------------------------------
__global__ void init_kernel() { if (threadIdx.x < E_) g_cnt[threadIdx.x] = 0; }

__global__ void gate_kernel(const float* __restrict__ x,
                            const float* __restrict__ gw) {
    int gtid = blockIdx.x * blockDim.x + threadIdx.x;
    int t = gtid >> 5, lane = gtid & 31;
    if (t >= N_) return;
    const float* xr = x + (size_t)t * D_;
    float acc[E_];
    #pragma unroll
    for (int e = 0; e < E_; e++) acc[e] = 0.f;
    for (int d = lane; d < D_; d += 32) {
        float xv = xr[d];
        #pragma unroll
        for (int e = 0; e < E_; e++) acc[e] = fmaf(xv, gw[d * E_ + e], acc[e]);
    }
    #pragma unroll
    for (int e = 0; e < E_; e++)
        #pragma unroll
        for (int o = 16; o > 0; o >>= 1)
            acc[e] += __shfl_xor_sync(0xffffffffu, acc[e], o);
    if (lane == 0) {
        int i0 = 0; float v0 = acc[0];
        #pragma unroll
        for (int e = 1; e < E_; e++) if (acc[e] > v0) { v0 = acc[e]; i0 = e; }
        int i1 = -1; float v1 = -1e30f;
        #pragma unroll
        for (int e = 0; e < E_; e++) if (e != i0 && acc[e] > v1) { v1 = acc[e]; i1 = e; }
        float e1 = expf(v1 - v0), inv = 1.f / (1.f + e1);
        int p0 = atomicAdd(&g_cnt[i0], 1);
        g_tok[i0 * N_ + p0] = t;  g_gate[i0 * N_ + p0] = inv;
        int p1 = atomicAdd(&g_cnt[i1], 1);
        g_tok[i1 * N_ + p1] = t;  g_gate[i1 * N_ + p1] = e1 * inv;
    }
}

// ---------------- grouped GEMM on HMMA (plain fp16, BK=128) -------------------
// PHASE 1: h = gelu(gather(x_h) @ w1t[e]^T + b1[e])
// PHASE 2: out += gate * (h @ w2t[e]^T + b2[e])   [split-K=2 over grid z]
template<int PHASE>
__global__ __launch_bounds__(NTHREADS, 1)
void moe_gemm_kernel(const float* __restrict__ bias_g, float* __restrict__ out) {
    constexpr int KT    = (PHASE == 1) ? D_ : F_;          // full K (row stride)
    constexpr int KTT   = (PHASE == 1) ? D_/BK : (F_/2)/BK; // 8 or 16 k-tiles
    constexpr int NFULL = (PHASE == 1) ? F_ : D_;

    int z = blockIdx.z;
    int e, split, kbase;
    if (PHASE == 1) { e = z;      split = 0;     kbase = 0; }
    else            { e = z >> 1; split = z & 1; kbase = split * (F_/2); }

    int cnt = g_cnt[e];
    int m0  = blockIdx.y * BM;
    if (m0 >= cnt) return;
    int n0  = blockIdx.x * BN;
    int off = 0;
    #pragma unroll
    for (int j = 0; j < E_; j++) if (j < e) off += g_cnt[j];

    extern __shared__ __align__(1024) char smem[];
    uint32_t sb = smem_u32(smem);
    int tid = threadIdx.x, wid = tid >> 5, lane = tid & 31;

    const __half* Ap = (PHASE == 1) ? g_x_h : g_h;
    const __half* Bp = ((PHASE == 1) ? g_w1t : g_w2t) + (size_t)e * (size_t)NFULL * KT;

    // ---- cp.async mapping: rows (tid>>4)+32i, chunk tid&15 (16B), 256B rows --
    int rbase = tid >> 4;              // 0..31
    int ch    = tid & 15;
    int csw   = ch ^ (rbase & 7);      // (32-row steps keep row&7 constant)
    uint32_t dst = (uint32_t)(rbase * 256 + csw * 16);   // +8192 per 32-row step

    const __half* a_p[4];
    #pragma unroll
    for (int i = 0; i < 4; i++) {
        int grow = min(m0 + rbase + 32 * i, cnt - 1);
        size_t arow = (PHASE == 1) ? (size_t)g_tok[e * N_ + grow]
                                   : (size_t)(off + grow);
        a_p[i] = Ap + arow * KT + ch * 8 + kbase;
    }
    const __half* b_p = Bp + (size_t)(n0 + rbase) * KT + ch * 8 + kbase;

    auto load_stage = [&](int kt, int slot) {
        uint32_t s0 = sb + slot * STAGE_BYTES;
        int koff = kt * BK;
        #pragma unroll
        for (int i = 0; i < 4; i++)
            cp16(s0 + OFF_A + dst + i * 8192u, a_p[i] + koff);
        #pragma unroll
        for (int i = 0; i < 8; i++)
            cp16(s0 + OFF_B + dst + i * 8192u, b_p + koff + i * (32 * KT));
    };

    // ---- fragment addresses: warp grid 4(m) x 4(n), tile 32x64, 256B rows ----
    int m_warp = (wid & 3) * 32;
    int n_warp = (wid >> 2) * 64;
    uint32_t a_rowb[2], b_rowb[4];
    #pragma unroll
    for (int mf = 0; mf < 2; mf++)
        a_rowb[mf] = (uint32_t)((m_warp + mf * 16 + (lane & 15)) * 256);
    #pragma unroll
    for (int q = 0; q < 4; q++)
        b_rowb[q] = (uint32_t)((n_warp + q * 16 + ((lane & 16) >> 1) + (lane & 7)) * 256);
    uint32_t a_chsel = (uint32_t)(lane >> 4);
    uint32_t b_chsel = (uint32_t)((lane >> 3) & 1);
    uint32_t lxor    = (uint32_t)(lane & 7);

    float acc[2][8][4];
    #pragma unroll
    for (int mf = 0; mf < 2; mf++)
        #pragma unroll
        for (int nb = 0; nb < 8; nb++)
            #pragma unroll
            for (int i = 0; i < 4; i++) acc[mf][nb][i] = 0.f;

    // ---- prologue ----
    load_stage(0, 0);
    cp_commit();

    // ---- main loop: one barrier per k-tile; load(kt+1) issued before compute.
    // Buffer (kt+1)&1 == (kt-1)&1 was last read by compute(kt-1); the barrier
    // at the top of iter kt orders all warps past compute(kt-1). ----
    for (int kt = 0; kt < KTT; kt++) {
        cp_wait<0>();
        __syncthreads();
        if (kt + 1 < KTT) {
            load_stage(kt + 1, (kt + 1) & 1);
            cp_commit();
        }

        uint32_t s0 = sb + (kt & 1) * STAGE_BYTES;
        #pragma unroll
        for (int ks = 0; ks < 8; ks++) {
            uint32_t ach = (((2 * (uint32_t)ks + a_chsel) ^ lxor) << 4);
            uint32_t bch = (((2 * (uint32_t)ks + b_chsel) ^ lxor) << 4);
            uint32_t af[2][4], bf[4][4];
            #pragma unroll
            for (int mf = 0; mf < 2; mf++)
                ldm4(af[mf][0], af[mf][1], af[mf][2], af[mf][3],
                     s0 + OFF_A + a_rowb[mf] + ach);
            #pragma unroll
            for (int q = 0; q < 4; q++)
                ldm4(bf[q][0], bf[q][1], bf[q][2], bf[q][3],
                     s0 + OFF_B + b_rowb[q] + bch);
            #pragma unroll
            for (int q = 0; q < 4; q++) {
                #pragma unroll
                for (int mf = 0; mf < 2; mf++) {
                    mma16816(acc[mf][2*q],   af[mf], bf[q][0], bf[q][1]);
                    mma16816(acc[mf][2*q+1], af[mf], bf[q][2], bf[q][3]);
                }
            }
        }
    }

    // ---- epilogue ----
    const float* bias = bias_g + (size_t)e * NFULL + n0;
    #pragma unroll
    for (int mf = 0; mf < 2; mf++) {
        #pragma unroll
        for (int hh = 0; hh < 2; hh++) {
            int lr = m_warp + mf * 16 + hh * 8 + (lane >> 2);
            int r  = m0 + lr;
            if (r >= cnt) continue;
            if (PHASE == 1) {
                __half* ph = g_h + (size_t)(off + r) * F_ + n0;
                #pragma unroll
                for (int nb = 0; nb < 8; nb++) {
                    int col = n_warp + nb * 8 + 2 * (lane & 3);
                    float2 bv = *(const float2*)(bias + col);
                    float v0 = gelu_f(acc[mf][nb][hh*2]     + bv.x);
                    float v1 = gelu_f(acc[mf][nb][hh*2 + 1] + bv.y);
                    *(uint32_t*)(ph + col) =
                        pack2(__float2half_rn(v0), __float2half_rn(v1));
                }
            } else {
                int   tok = g_tok[e * N_ + r];
                float gv  = g_gate[e * N_ + r];
                float* orow = out + (size_t)tok * D_ + n0;
                #pragma unroll
                for (int nb = 0; nb < 8; nb++) {
                    int col = n_warp + nb * 8 + 2 * (lane & 3);
                    float bx = 0.f, by = 0.f;
                    if (split == 0) {
                        float2 bv = *(const float2*)(bias + col);
                        bx = bv.x; by = bv.y;
                    }
                    atomicAdd(orow + col,     gv * (acc[mf][nb][hh*2]     + bx));
                    atomicAdd(orow + col + 1, gv * (acc[mf][nb][hh*2 + 1] + by));
                }
            }
        }
    }
}

// ---------------- launch --------------------------------------------------------
extern "C" void kernel_launch(void* const* d_in, const int* in_sizes, int n_in,
                              void* d_out, int out_size) {
    const float* x  = (const float*)d_in[0];
    const float* gw = (const float*)d_in[1];
    const float* w1 = (const float*)d_in[2];
    const float* b1 = (const float*)d_in[3];
    const float* w2 = (const float*)d_in[4];
    const float* b2 = (const float*)d_in[5];
    float* out = (float*)d_out;

    cudaFuncSetAttribute(moe_gemm_kernel<1>,
                         cudaFuncAttributeMaxDynamicSharedMemorySize, SMEM_TOTAL);
    cudaFuncSetAttribute(moe_gemm_kernel<2>,
                         cudaFuncAttributeMaxDynamicSharedMemorySize, SMEM_TOTAL);

    cudaMemsetAsync(out, 0, (size_t)out_size * sizeof(float), 0);
    prep_all_kernel<<<XBLKS + W1BLKS + W2BLKS, PT>>>(x, w1, w2);
    init_kernel<<<1, 32>>>();
    gate_kernel<<<(N_ * 32) / 256, 256>>>(x, gw);

    dim3 g1(F_/BN, N_/BM, E_);        // (16, 64, 8), cnt-guarded
    moe_gemm_kernel<1><<<g1, NTHREADS, SMEM_TOTAL>>>(b1, out);

    dim3 g2(D_/BN, N_/BM, E_ * 2);    // (4, 64, 16): split-K=2, cnt-guarded
    moe_gemm_kernel<2><<<g2, NTHREADS, SMEM_TOTAL>>>(b2, out);
}